// round 14
// baseline (speedup 1.0000x reference)
#include <cuda_runtime.h>
#include <cstdint>

// ---------------- problem constants ----------------
#define BJ   128          // batch
#define JJ   22           // joints
#define EE   8            // experts
#define PAIRS (JJ*EE)     // 176
#define DT_  9
#define DD   64
#define D_IN  2304        // DT*K*D
#define D_OUT 576         // DT*D
#define H1_  256
#define H2_  128

// ---------------- scratch (static device memory; no allocations) ----------------
#define OFF_INP  0
#define OFF_H1   6488064
#define OFF_H2   12255232
#define OFF_MU   15138816
#define OFF_LV   18022400
#define OFF_G    20905984
#define OFF_XHAT 26673152
#define SCRATCH_TOTAL 39649280

__device__ __align__(16) float g_scratch[SCRATCH_TOTAL];
__device__ float g_err[PAIRS * BJ];

// TF32 rounding (cvt.rna — bit-identical to R12; DO NOT CHANGE: argmin knife rows)
__device__ __forceinline__ float tf32r(float f) {
    uint32_t u;
    asm("cvt.rna.tf32.f32 %0, %1;" : "=r"(u) : "f"(f));
    return __uint_as_float(u);
}

// Packed dual fp32 FMA: two independent IEEE rn-fused FMAs per instruction.
// Bit-identical per lane to fmaf — only the issue rate changes.
#define FMA_F32X2(d, a, b, c) \
    asm("fma.rn.f32x2 %0, %1, %2, %3;" : "=l"(d) : "l"(a), "l"(b), "l"(c))

// ---------------- gather: inp[j][b][t*256+k*64+d] = x[b][t][nbr[j][k]][d] ----------------
__global__ void gather_kernel(const float* __restrict__ x,
                              const int* __restrict__ nbr,
                              float* __restrict__ inp)
{
    int idx = blockIdx.x * blockDim.x + threadIdx.x;
    if (idx >= JJ * BJ * D_IN) return;
    int j = idx / (BJ * D_IN);
    int r = idx - j * (BJ * D_IN);
    int b = r / D_IN;
    int c = r - b * D_IN;
    int t = c >> 8;          // / 256
    int k = (c >> 6) & 3;
    int d = c & 63;
    int n = nbr[j * 4 + k];
    inp[idx] = x[(((size_t)b * DT_ + t) * JJ + n) * DD + d];
}

// ---------------- batched GEMM, TF32 inputs, fp32 accumulate via fma.rn.f32x2 ----------
// C = act(tf32(A) @ tf32(W) + bias). Per-output-element accumulation chain is the
// SAME k-ascending sequence of rn-FMAs as R12 -> xhat is bit-identical to R12.
// Optional second problem set (W2/bias2/C2) for fused independent GEMMs sharing A:
// blocks with blockIdx.y >= nb1 compute the second set.
template<bool RELU>
__global__ void __launch_bounds__(256, 2) gemm_f2(
    const float* __restrict__ A,
    const float* __restrict__ W,  const float* __restrict__ bias,  float* __restrict__ C,
    const float* __restrict__ W2, const float* __restrict__ bias2, float* __restrict__ C2,
    int nb1, int K, int N, int a_div)
{
    constexpr int BM = 128, BN = 128, BK = 16;
    int pr = blockIdx.y;
    const float* Wsel = W; const float* bsel = bias; float* Csel = C;
    int pair = pr;
    if (pr >= nb1) { pair = pr - nb1; Wsel = W2; bsel = bias2; Csel = C2; }

    const int n0 = blockIdx.x * BN;
    const int tid = threadIdx.x;

    const float* Ap = A + (size_t)(pair / a_div) * (size_t)BM * K;
    const float* Wp = Wsel + (size_t)pair * (size_t)K * N;
    const float* bp = bsel + (size_t)pair * N;
    float* Cp = Csel + (size_t)pair * (size_t)BM * N;

    // A stored duplicated: As2[k][2m] = As2[k][2m+1] = a(m,k)  (for packed broadcast)
    __shared__ float As2[BK][2 * BM + 8];
    __shared__ float Bs[BK][BN + 8];

    const int a_row = tid >> 1;          // 0..127
    const int a_k   = (tid & 1) * 8;     // 0 or 8
    const int b_row = tid >> 4;          // 0..15
    const int b_c4  = tid & 15;          // 0..15

    const int rm0 = (tid >> 4) * 8;      // 0..120
    const int rn0 = (tid & 15) * 8;      // 0..120

    unsigned long long accp[8][4];       // accp[i][j2] = (acc[i][2j2], acc[i][2j2+1])
    #pragma unroll
    for (int i = 0; i < 8; i++)
        #pragma unroll
        for (int j2 = 0; j2 < 4; j2++) accp[i][j2] = 0ULL;

    for (int kk = 0; kk < K; kk += BK) {
        // load A tile, TF32-round, store duplicated
        #pragma unroll
        for (int v = 0; v < 2; v++) {
            float4 a = *reinterpret_cast<const float4*>(
                Ap + (size_t)a_row * K + kk + a_k + v * 4);
            float t0 = tf32r(a.x), t1 = tf32r(a.y), t2 = tf32r(a.z), t3 = tf32r(a.w);
            As2[a_k + v*4 + 0][2*a_row] = t0; As2[a_k + v*4 + 0][2*a_row + 1] = t0;
            As2[a_k + v*4 + 1][2*a_row] = t1; As2[a_k + v*4 + 1][2*a_row + 1] = t1;
            As2[a_k + v*4 + 2][2*a_row] = t2; As2[a_k + v*4 + 2][2*a_row + 1] = t2;
            As2[a_k + v*4 + 3][2*a_row] = t3; As2[a_k + v*4 + 3][2*a_row + 1] = t3;
        }
        // load B tile (N-guarded), TF32-round
        #pragma unroll
        for (int v = 0; v < 2; v++) {
            int col = b_c4 * 4 + v * 64;
            float4 b = make_float4(0.f, 0.f, 0.f, 0.f);
            if (n0 + col < N)
                b = *reinterpret_cast<const float4*>(
                    Wp + (size_t)(kk + b_row) * N + n0 + col);
            Bs[b_row][col + 0] = tf32r(b.x);
            Bs[b_row][col + 1] = tf32r(b.y);
            Bs[b_row][col + 2] = tf32r(b.z);
            Bs[b_row][col + 3] = tf32r(b.w);
        }
        __syncthreads();

        #pragma unroll
        for (int k = 0; k < BK; k++) {
            ulonglong2 a0 = *reinterpret_cast<const ulonglong2*>(&As2[k][2*rm0]);
            ulonglong2 a1 = *reinterpret_cast<const ulonglong2*>(&As2[k][2*rm0 + 4]);
            ulonglong2 a2 = *reinterpret_cast<const ulonglong2*>(&As2[k][2*rm0 + 8]);
            ulonglong2 a3 = *reinterpret_cast<const ulonglong2*>(&As2[k][2*rm0 + 12]);
            ulonglong2 b0 = *reinterpret_cast<const ulonglong2*>(&Bs[k][rn0]);
            ulonglong2 b1 = *reinterpret_cast<const ulonglong2*>(&Bs[k][rn0 + 4]);
            unsigned long long ap[8] = {a0.x, a0.y, a1.x, a1.y, a2.x, a2.y, a3.x, a3.y};
            unsigned long long bp2[4] = {b0.x, b0.y, b1.x, b1.y};
            #pragma unroll
            for (int i = 0; i < 8; i++)
                #pragma unroll
                for (int j2 = 0; j2 < 4; j2++)
                    FMA_F32X2(accp[i][j2], ap[i], bp2[j2], accp[i][j2]);
        }
        __syncthreads();
    }

    // epilogue: unpack, bias (+ReLU), guarded store
    #pragma unroll
    for (int j2 = 0; j2 < 4; j2++) {
        int c0 = n0 + rn0 + 2 * j2;
        int c1 = c0 + 1;
        float bv0 = (c0 < N) ? bp[c0] : 0.f;
        float bv1 = (c1 < N) ? bp[c1] : 0.f;
        #pragma unroll
        for (int i = 0; i < 8; i++) {
            unsigned long long v = accp[i][j2];
            float lo = __uint_as_float((uint32_t)v);
            float hi = __uint_as_float((uint32_t)(v >> 32));
            float v0 = lo + bv0;
            float v1 = hi + bv1;
            if (RELU) { v0 = fmaxf(v0, 0.f); v1 = fmaxf(v1, 0.f); }
            size_t rowoff = (size_t)(rm0 + i) * N;
            if (c0 < N) Cp[rowoff + c0] = v0;
            if (c1 < N) Cp[rowoff + c1] = v1;
        }
    }
}

// ---------------- err[p][b]: XLA:GPU row-reduction emitter order (bit-exact, DO NOT TOUCH)
__global__ void err_kernel(const float* __restrict__ xhat,
                           const float* __restrict__ x,
                           float* __restrict__ err)
{
    int w = (blockIdx.x * blockDim.x + threadIdx.x) >> 5;
    int lane = threadIdx.x & 31;
    if (w >= PAIRS * BJ) return;
    int p = w / BJ;
    int b = w - p * BJ;
    int j = p / EE;
    const float* xh = xhat + ((size_t)p * BJ + b) * D_OUT;
    const float* xb = x + (size_t)b * DT_ * JJ * DD + (size_t)j * DD;

    float acc = 0.f;
    #pragma unroll
    for (int k = 0; k < 9; k++) {
        int i0 = 2 * lane + 64 * k;
        int t0 = i0 >> 6, d0i = i0 & 63;
        int i1 = i0 + 1;
        int t1 = i1 >> 6, d1i = i1 & 63;
        float tg0 = __ldg(xb + (size_t)t0 * JJ * DD + d0i);
        float tg1 = __ldg(xb + (size_t)t1 * JJ * DD + d1i);
        float d0 = __fsub_rn(__ldg(xh + i0), tg0);
        float d1 = __fsub_rn(__ldg(xh + i1), tg1);
        acc = fmaf(d0, d0, acc);
        acc = fmaf(d1, d1, acc);
    }
    #pragma unroll
    for (int o = 16; o > 0; o >>= 1)
        acc = __fadd_rn(acc, __shfl_down_sync(0xffffffffu, acc, o));
    if (lane == 0) err[(size_t)p * BJ + b] = __fdiv_rn(acc, 576.0f);
}

// ---------------- select: argmin over e (strict <, ties -> lowest index) ----------------
// out layout (float32): mu(B,J,128) | lv(B,J,128) | xhat(B,DT,J,D) | idx(B,J)
#define OUT_MU   0
#define OUT_LV   360448
#define OUT_XH   720896
#define OUT_IDX  2342912
__global__ void select_kernel(const float* __restrict__ mu,
                              const float* __restrict__ lv,
                              const float* __restrict__ xhat,
                              const float* __restrict__ err,
                              float* __restrict__ out)
{
    int j = blockIdx.x;
    int b = blockIdx.y;
    int tid = threadIdx.x;  // 128

    float best = err[(size_t)(j * EE + 0) * BJ + b];
    int bi = 0;
    #pragma unroll
    for (int e = 1; e < EE; e++) {
        float v = err[(size_t)(j * EE + e) * BJ + b];
        if (v < best) { best = v; bi = e; }
    }
    int p = j * EE + bi;

    size_t base = ((size_t)b * JJ + j) * H2_;
    out[OUT_MU + base + tid] = mu[((size_t)p * BJ + b) * H2_ + tid];
    out[OUT_LV + base + tid] = lv[((size_t)p * BJ + b) * H2_ + tid];

    const float* xh = xhat + ((size_t)p * BJ + b) * D_OUT;
    for (int i = tid; i < D_OUT; i += 128) {
        int t = i >> 6, d = i & 63;
        out[OUT_XH + (((size_t)b * DT_ + t) * JJ + j) * DD + d] = xh[i];
    }
    if (tid == 0) out[OUT_IDX + (size_t)b * JJ + j] = (float)bi;
}

// ---------------- launch ----------------
extern "C" void kernel_launch(void* const* d_in, const int* in_sizes, int n_in,
                              void* d_out, int out_size)
{
    const float* x         = (const float*)d_in[0];
    const int*   neighbors = (const int*)d_in[1];
    const float* W_e1 = (const float*)d_in[2];
    const float* b_e1 = (const float*)d_in[3];
    const float* W_e2 = (const float*)d_in[4];
    const float* b_e2 = (const float*)d_in[5];
    const float* W_mu = (const float*)d_in[6];
    const float* b_mu = (const float*)d_in[7];
    const float* W_lv = (const float*)d_in[8];
    const float* b_lv = (const float*)d_in[9];
    const float* W_d1 = (const float*)d_in[10];
    const float* b_d1 = (const float*)d_in[11];
    const float* W_d2 = (const float*)d_in[12];
    const float* b_d2 = (const float*)d_in[13];
    float* out = (float*)d_out;

    float* scratch = nullptr;
    cudaGetSymbolAddress((void**)&scratch, g_scratch);
    float* errbuf = nullptr;
    cudaGetSymbolAddress((void**)&errbuf, g_err);

    float* s_inp  = scratch + OFF_INP;
    float* s_h1   = scratch + OFF_H1;
    float* s_h2   = scratch + OFF_H2;
    float* s_mu   = scratch + OFF_MU;
    float* s_lv   = scratch + OFF_LV;
    float* s_g    = scratch + OFF_G;
    float* s_xhat = scratch + OFF_XHAT;

    // 1. gather neighbor features
    {
        int total = JJ * BJ * D_IN;
        gather_kernel<<<(total + 255) / 256, 256>>>(x, neighbors, s_inp);
    }
    // 2. h1 = relu(inp @ W_e1 + b_e1)   [K=2304, N=256], A shared across e (a_div=8)
    gemm_f2<true ><<<dim3(2, PAIRS), 256>>>(s_inp, W_e1, b_e1, s_h1,
                                            nullptr, nullptr, nullptr,
                                            PAIRS, D_IN, H1_, EE);
    // 3. h2 = relu(h1 @ W_e2 + b_e2)    [K=256, N=128]
    gemm_f2<true ><<<dim3(1, PAIRS), 256>>>(s_h1, W_e2, b_e2, s_h2,
                                            nullptr, nullptr, nullptr,
                                            PAIRS, H1_, H2_, 1);
    // 4+5. mu & lv fused (independent, both read h2)  [K=128, N=128]
    gemm_f2<false><<<dim3(1, 2 * PAIRS), 256>>>(s_h2, W_mu, b_mu, s_mu,
                                                W_lv, b_lv, s_lv,
                                                PAIRS, H2_, H2_, 1);
    // 6. g = relu(mu @ W_d1 + b_d1)     [K=128, N=256]
    gemm_f2<true ><<<dim3(2, PAIRS), 256>>>(s_mu, W_d1, b_d1, s_g,
                                            nullptr, nullptr, nullptr,
                                            PAIRS, H2_, H1_, 1);
    // 7. xhat = g @ W_d2 + b_d2         [K=256, N=576]
    gemm_f2<false><<<dim3(5, PAIRS), 256>>>(s_g, W_d2, b_d2, s_xhat,
                                            nullptr, nullptr, nullptr,
                                            PAIRS, H1_, D_OUT, 1);
    // 8. per-(p,b) reconstruction error: XLA:GPU vec2 warp row-reduce
    {
        int warps = PAIRS * BJ;                 // 22528
        err_kernel<<<(warps * 32 + 255) / 256, 256>>>(s_xhat, x, errbuf);
    }
    // 9. argmin (ties -> lowest index) + gather outputs
    select_kernel<<<dim3(JJ, BJ), 128>>>(s_mu, s_lv, s_xhat, errbuf, out);
}

// round 15
// speedup vs baseline: 1.5091x; 1.5091x over previous
#include <cuda_runtime.h>
#include <cstdint>

// ---------------- problem constants ----------------
#define BJ   128          // batch
#define JJ   22           // joints
#define EE   8            // experts
#define PAIRS (JJ*EE)     // 176
#define DT_  9
#define DD   64
#define D_IN  2304        // DT*K*D
#define D_OUT 576         // DT*D
#define H1_  256
#define H2_  128

// ---------------- scratch (static device memory; no allocations) ----------------
#define OFF_INP  0
#define OFF_H1   6488064
#define OFF_H2   12255232
#define OFF_MU   15138816
#define OFF_LV   18022400
#define OFF_G    20905984
#define OFF_XHAT 26673152
#define SCRATCH_TOTAL 39649280

__device__ __align__(16) float g_scratch[SCRATCH_TOTAL];
__device__ float g_err[PAIRS * BJ];

// TF32 rounding (cvt.rna — bit-identical across all rounds; DO NOT CHANGE)
__device__ __forceinline__ float tf32r(float f) {
    uint32_t u;
    asm("cvt.rna.tf32.f32 %0, %1;" : "=r"(u) : "f"(f));
    return __uint_as_float(u);
}

__device__ __forceinline__ void mma_tf32(float* c, const uint32_t* a, const uint32_t* b) {
    asm volatile(
        "mma.sync.aligned.m16n8k8.row.col.f32.tf32.tf32.f32 "
        "{%0,%1,%2,%3}, {%4,%5,%6,%7}, {%8,%9}, {%0,%1,%2,%3};\n"
        : "+f"(c[0]), "+f"(c[1]), "+f"(c[2]), "+f"(c[3])
        : "r"(a[0]), "r"(a[1]), "r"(a[2]), "r"(a[3]), "r"(b[0]), "r"(b[1]));
}

// ---------------- gather: inp[j][b][t*256+k*64+d] = x[b][t][nbr[j][k]][d] ----------------
__global__ void gather_kernel(const float* __restrict__ x,
                              const int* __restrict__ nbr,
                              float* __restrict__ inp)
{
    int idx = blockIdx.x * blockDim.x + threadIdx.x;
    if (idx >= JJ * BJ * D_IN) return;
    int j = idx / (BJ * D_IN);
    int r = idx - j * (BJ * D_IN);
    int b = r / D_IN;
    int c = r - b * D_IN;
    int t = c >> 8;          // / 256
    int k = (c >> 6) & 3;
    int d = c & 63;
    int n = nbr[j * 4 + k];
    inp[idx] = x[(((size_t)b * DT_ + t) * JJ + n) * DD + d];
}

// ---------------- batched FFMA GEMM (R12-exact numerics; layers 2-7) ----------------
// C[p] = act(tf32(A[p/a_div]) @ tf32(W[p]) + bias[p])
template<bool RELU>
__global__ void __launch_bounds__(256, 2) gemm_bias(
    const float* __restrict__ A, const float* __restrict__ W,
    const float* __restrict__ bias, float* __restrict__ C,
    int K, int N, int a_div)
{
    constexpr int BM = 128, BN = 128, BK = 16;
    const int pair = blockIdx.y;
    const int n0 = blockIdx.x * BN;
    const int tid = threadIdx.x;

    const float* Ap = A + (size_t)(pair / a_div) * (size_t)BM * K;
    const float* Wp = W + (size_t)pair * (size_t)K * N;
    const float* bp = bias + (size_t)pair * N;
    float* Cp = C + (size_t)pair * (size_t)BM * N;

    __shared__ float As[BK][BM];
    __shared__ float Bs[BK][BN];

    const int a_row = tid >> 1;
    const int a_k   = (tid & 1) * 8;
    const int b_row = tid >> 4;
    const int b_c4  = tid & 15;

    const int rm0 = (tid >> 4) * 8;
    const int rn0 = (tid & 15) * 8;

    float acc[8][8];
    #pragma unroll
    for (int i = 0; i < 8; i++)
        #pragma unroll
        for (int j = 0; j < 8; j++) acc[i][j] = 0.f;

    for (int kk = 0; kk < K; kk += BK) {
        #pragma unroll
        for (int v = 0; v < 2; v++) {
            float4 a = *reinterpret_cast<const float4*>(
                Ap + (size_t)a_row * K + kk + a_k + v * 4);
            As[a_k + v * 4 + 0][a_row] = tf32r(a.x);
            As[a_k + v * 4 + 1][a_row] = tf32r(a.y);
            As[a_k + v * 4 + 2][a_row] = tf32r(a.z);
            As[a_k + v * 4 + 3][a_row] = tf32r(a.w);
        }
        #pragma unroll
        for (int v = 0; v < 2; v++) {
            int col = b_c4 * 4 + v * 64;
            float4 b = make_float4(0.f, 0.f, 0.f, 0.f);
            if (n0 + col < N)
                b = *reinterpret_cast<const float4*>(
                    Wp + (size_t)(kk + b_row) * N + n0 + col);
            Bs[b_row][col + 0] = tf32r(b.x);
            Bs[b_row][col + 1] = tf32r(b.y);
            Bs[b_row][col + 2] = tf32r(b.z);
            Bs[b_row][col + 3] = tf32r(b.w);
        }
        __syncthreads();

        #pragma unroll
        for (int k = 0; k < BK; k++) {
            float ra[8], rb[8];
            #pragma unroll
            for (int i = 0; i < 2; i++) {
                float4 t4 = *reinterpret_cast<const float4*>(&As[k][rm0 + i * 4]);
                ra[i*4+0] = t4.x; ra[i*4+1] = t4.y; ra[i*4+2] = t4.z; ra[i*4+3] = t4.w;
            }
            #pragma unroll
            for (int i = 0; i < 2; i++) {
                float4 t4 = *reinterpret_cast<const float4*>(&Bs[k][rn0 + i * 4]);
                rb[i*4+0] = t4.x; rb[i*4+1] = t4.y; rb[i*4+2] = t4.z; rb[i*4+3] = t4.w;
            }
            #pragma unroll
            for (int i = 0; i < 8; i++)
                #pragma unroll
                for (int j = 0; j < 8; j++)
                    acc[i][j] = fmaf(ra[i], rb[j], acc[i][j]);
        }
        __syncthreads();
    }

    #pragma unroll
    for (int j = 0; j < 8; j++) {
        int n = n0 + rn0 + j;
        if (n < N) {
            float bv = bp[n];
            #pragma unroll
            for (int i = 0; i < 8; i++) {
                float v = acc[i][j] + bv;
                if (RELU) v = fmaxf(v, 0.f);
                Cp[(size_t)(rm0 + i) * N + n] = v;
            }
        }
    }
}

// ---------------- TF32 tensor-core GEMM (layer e1 only; lottery draw) ----------------
// Block 128x128, 8 warps (2x4), each warp 64x32 via 4x4 m16n8k8 tiles, ascending-k chain.
template<bool RELU>
__global__ void __launch_bounds__(256) gemm_mma(
    const float* __restrict__ A, const float* __restrict__ W,
    const float* __restrict__ bias, float* __restrict__ C,
    int K, int N, int a_div)
{
    constexpr int BM = 128, BN = 128, BK = 16;
    const int pair = blockIdx.y;
    const int n0 = blockIdx.x * BN;
    const int tid = threadIdx.x;
    const int wid = tid >> 5;
    const int lane = tid & 31;
    const int g  = lane >> 2;
    const int tg = lane & 3;

    const int wm0 = (wid & 1) * 64;
    const int wn0 = (wid >> 1) * 32;

    const float* Ap = A + (size_t)(pair / a_div) * (size_t)BM * K;
    const float* Wp = W + (size_t)pair * (size_t)K * N;
    const float* bp = bias + (size_t)pair * N;
    float* Cp = C + (size_t)pair * (size_t)BM * N;

    __shared__ float As[BK][BM + 4];
    __shared__ float Bs[BK][BN + 4];

    float acc[4][4][4];
    #pragma unroll
    for (int mi = 0; mi < 4; mi++)
        #pragma unroll
        for (int ni = 0; ni < 4; ni++)
            #pragma unroll
            for (int r = 0; r < 4; r++) acc[mi][ni][r] = 0.f;

    for (int kk = 0; kk < K; kk += BK) {
        #pragma unroll
        for (int v = 0; v < 2; v++) {
            int f4i = tid * 2 + v;
            int row = f4i >> 2;
            int kc  = (f4i & 3) * 4;
            float4 a = *reinterpret_cast<const float4*>(Ap + (size_t)row * K + kk + kc);
            As[kc + 0][row] = tf32r(a.x);
            As[kc + 1][row] = tf32r(a.y);
            As[kc + 2][row] = tf32r(a.z);
            As[kc + 3][row] = tf32r(a.w);
        }
        #pragma unroll
        for (int v = 0; v < 2; v++) {
            int f4i = tid * 2 + v;
            int krow = f4i >> 5;
            int nc   = (f4i & 31) * 4;
            float4 b = make_float4(0.f, 0.f, 0.f, 0.f);
            if (n0 + nc < N)
                b = *reinterpret_cast<const float4*>(Wp + (size_t)(kk + krow) * N + n0 + nc);
            Bs[krow][nc + 0] = tf32r(b.x);
            Bs[krow][nc + 1] = tf32r(b.y);
            Bs[krow][nc + 2] = tf32r(b.z);
            Bs[krow][nc + 3] = tf32r(b.w);
        }
        __syncthreads();

        #pragma unroll
        for (int ks = 0; ks < 2; ks++) {
            const int kb = ks * 8;
            uint32_t af[4][4], bf[4][2];
            #pragma unroll
            for (int mi = 0; mi < 4; mi++) {
                int mb = wm0 + mi * 16;
                af[mi][0] = __float_as_uint(As[kb + tg    ][mb + g    ]);
                af[mi][1] = __float_as_uint(As[kb + tg    ][mb + g + 8]);
                af[mi][2] = __float_as_uint(As[kb + tg + 4][mb + g    ]);
                af[mi][3] = __float_as_uint(As[kb + tg + 4][mb + g + 8]);
            }
            #pragma unroll
            for (int ni = 0; ni < 4; ni++) {
                int nb = wn0 + ni * 8;
                bf[ni][0] = __float_as_uint(Bs[kb + tg    ][nb + g]);
                bf[ni][1] = __float_as_uint(Bs[kb + tg + 4][nb + g]);
            }
            #pragma unroll
            for (int mi = 0; mi < 4; mi++)
                #pragma unroll
                for (int ni = 0; ni < 4; ni++)
                    mma_tf32(acc[mi][ni], af[mi], bf[ni]);
        }
        __syncthreads();
    }

    #pragma unroll
    for (int mi = 0; mi < 4; mi++) {
        #pragma unroll
        for (int ni = 0; ni < 4; ni++) {
            int row0 = wm0 + mi * 16 + g;
            int col0 = n0 + wn0 + ni * 8 + tg * 2;
            #pragma unroll
            for (int r = 0; r < 4; r++) {
                int row = row0 + (r >> 1) * 8;
                int col = col0 + (r & 1);
                if (col < N) {
                    float v = acc[mi][ni][r] + bp[col];
                    if (RELU) v = fmaxf(v, 0.f);
                    Cp[(size_t)row * N + col] = v;
                }
            }
        }
    }
}

// ---------------- err[p][b]: XLA:GPU row-reduction emitter order (bit-exact, DO NOT TOUCH)
__global__ void err_kernel(const float* __restrict__ xhat,
                           const float* __restrict__ x,
                           float* __restrict__ err)
{
    int w = (blockIdx.x * blockDim.x + threadIdx.x) >> 5;
    int lane = threadIdx.x & 31;
    if (w >= PAIRS * BJ) return;
    int p = w / BJ;
    int b = w - p * BJ;
    int j = p / EE;
    const float* xh = xhat + ((size_t)p * BJ + b) * D_OUT;
    const float* xb = x + (size_t)b * DT_ * JJ * DD + (size_t)j * DD;

    float acc = 0.f;
    #pragma unroll
    for (int k = 0; k < 9; k++) {
        int i0 = 2 * lane + 64 * k;
        int t0 = i0 >> 6, d0i = i0 & 63;
        int i1 = i0 + 1;
        int t1 = i1 >> 6, d1i = i1 & 63;
        float tg0 = __ldg(xb + (size_t)t0 * JJ * DD + d0i);
        float tg1 = __ldg(xb + (size_t)t1 * JJ * DD + d1i);
        float d0 = __fsub_rn(__ldg(xh + i0), tg0);
        float d1 = __fsub_rn(__ldg(xh + i1), tg1);
        acc = fmaf(d0, d0, acc);
        acc = fmaf(d1, d1, acc);
    }
    #pragma unroll
    for (int o = 16; o > 0; o >>= 1)
        acc = __fadd_rn(acc, __shfl_down_sync(0xffffffffu, acc, o));
    if (lane == 0) err[(size_t)p * BJ + b] = __fdiv_rn(acc, 576.0f);
}

// ---------------- select: argmin over e (strict <, ties -> lowest index) ----------------
// out layout (float32): mu(B,J,128) | lv(B,J,128) | xhat(B,DT,J,D) | idx(B,J)
#define OUT_MU   0
#define OUT_LV   360448
#define OUT_XH   720896
#define OUT_IDX  2342912
__global__ void select_kernel(const float* __restrict__ mu,
                              const float* __restrict__ lv,
                              const float* __restrict__ xhat,
                              const float* __restrict__ err,
                              float* __restrict__ out)
{
    int j = blockIdx.x;
    int b = blockIdx.y;
    int tid = threadIdx.x;  // 128

    float best = err[(size_t)(j * EE + 0) * BJ + b];
    int bi = 0;
    #pragma unroll
    for (int e = 1; e < EE; e++) {
        float v = err[(size_t)(j * EE + e) * BJ + b];
        if (v < best) { best = v; bi = e; }
    }
    int p = j * EE + bi;

    size_t base = ((size_t)b * JJ + j) * H2_;
    out[OUT_MU + base + tid] = mu[((size_t)p * BJ + b) * H2_ + tid];
    out[OUT_LV + base + tid] = lv[((size_t)p * BJ + b) * H2_ + tid];

    const float* xh = xhat + ((size_t)p * BJ + b) * D_OUT;
    for (int i = tid; i < D_OUT; i += 128) {
        int t = i >> 6, d = i & 63;
        out[OUT_XH + (((size_t)b * DT_ + t) * JJ + j) * DD + d] = xh[i];
    }
    if (tid == 0) out[OUT_IDX + (size_t)b * JJ + j] = (float)bi;
}

// ---------------- launch ----------------
extern "C" void kernel_launch(void* const* d_in, const int* in_sizes, int n_in,
                              void* d_out, int out_size)
{
    const float* x         = (const float*)d_in[0];
    const int*   neighbors = (const int*)d_in[1];
    const float* W_e1 = (const float*)d_in[2];
    const float* b_e1 = (const float*)d_in[3];
    const float* W_e2 = (const float*)d_in[4];
    const float* b_e2 = (const float*)d_in[5];
    const float* W_mu = (const float*)d_in[6];
    const float* b_mu = (const float*)d_in[7];
    const float* W_lv = (const float*)d_in[8];
    const float* b_lv = (const float*)d_in[9];
    const float* W_d1 = (const float*)d_in[10];
    const float* b_d1 = (const float*)d_in[11];
    const float* W_d2 = (const float*)d_in[12];
    const float* b_d2 = (const float*)d_in[13];
    float* out = (float*)d_out;

    float* scratch = nullptr;
    cudaGetSymbolAddress((void**)&scratch, g_scratch);
    float* errbuf = nullptr;
    cudaGetSymbolAddress((void**)&errbuf, g_err);

    float* s_inp  = scratch + OFF_INP;
    float* s_h1   = scratch + OFF_H1;
    float* s_h2   = scratch + OFF_H2;
    float* s_mu   = scratch + OFF_MU;
    float* s_lv   = scratch + OFF_LV;
    float* s_g    = scratch + OFF_G;
    float* s_xhat = scratch + OFF_XHAT;

    // 1. gather neighbor features
    {
        int total = JJ * BJ * D_IN;
        gather_kernel<<<(total + 255) / 256, 256>>>(x, neighbors, s_inp);
    }
    // 2. h1 = relu(inp @ W_e1 + b_e1)   [K=2304, N=256] — TENSOR CORES (lottery draw)
    gemm_mma<true ><<<dim3(2, PAIRS), 256>>>(s_inp, W_e1, b_e1, s_h1, D_IN, H1_, EE);
    // 3. h2 = relu(h1 @ W_e2 + b_e2)    [K=256, N=128] — R12-exact FFMA
    gemm_bias<true ><<<dim3(1, PAIRS), 256>>>(s_h1, W_e2, b_e2, s_h2, H1_, H2_, 1);
    // 4. mu = h2 @ W_mu + b_mu          [K=128, N=128]
    gemm_bias<false><<<dim3(1, PAIRS), 256>>>(s_h2, W_mu, b_mu, s_mu, H2_, H2_, 1);
    // 5. lv = h2 @ W_lv + b_lv
    gemm_bias<false><<<dim3(1, PAIRS), 256>>>(s_h2, W_lv, b_lv, s_lv, H2_, H2_, 1);
    // 6. g = relu(mu @ W_d1 + b_d1)     [K=128, N=256]
    gemm_bias<true ><<<dim3(2, PAIRS), 256>>>(s_mu, W_d1, b_d1, s_g, H2_, H1_, 1);
    // 7. xhat = g @ W_d2 + b_d2         [K=256, N=576]
    gemm_bias<false><<<dim3(5, PAIRS), 256>>>(s_g, W_d2, b_d2, s_xhat, H1_, D_OUT, 1);
    // 8. per-(p,b) reconstruction error: XLA:GPU vec2 warp row-reduce
    {
        int warps = PAIRS * BJ;                 // 22528
        err_kernel<<<(warps * 32 + 255) / 256, 256>>>(s_xhat, x, errbuf);
    }
    // 9. argmin (ties -> lowest index) + gather outputs
    select_kernel<<<dim3(JJ, BJ), 128>>>(s_mu, s_lv, s_xhat, errbuf, out);
}

// round 17
// speedup vs baseline: 1.9585x; 1.2978x over previous
#include <cuda_runtime.h>
#include <cstdint>

// ---------------- problem constants ----------------
#define BJ   128
#define JJ   22
#define EE   8
#define PAIRS (JJ*EE)
#define DT_  9
#define DD   64
#define D_IN  2304
#define D_OUT 576
#define H1_  256
#define H2_  128

// ---------------- scratch ----------------
#define OFF_INP  0
#define OFF_H1   6488064
#define OFF_H2   12255232
#define OFF_MU   15138816
#define OFF_LV   18022400
#define OFF_G    20905984
#define OFF_XHAT 26673152
#define SCRATCH_TOTAL 39649280

__device__ __align__(16) float g_scratch[SCRATCH_TOTAL];
__device__ float g_err[PAIRS * BJ];

// TF32 rounding (cvt.rna — DO NOT CHANGE)
__device__ __forceinline__ float tf32r(float f) {
    uint32_t u;
    asm("cvt.rna.tf32.f32 %0, %1;" : "=r"(u) : "f"(f));
    return __uint_as_float(u);
}

__device__ __forceinline__ void mma_tf32(float* c, const uint32_t* a, const uint32_t* b) {
    asm volatile(
        "mma.sync.aligned.m16n8k8.row.col.f32.tf32.tf32.f32 "
        "{%0,%1,%2,%3}, {%4,%5,%6,%7}, {%8,%9}, {%0,%1,%2,%3};\n"
        : "+f"(c[0]), "+f"(c[1]), "+f"(c[2]), "+f"(c[3])
        : "r"(a[0]), "r"(a[1]), "r"(a[2]), "r"(a[3]), "r"(b[0]), "r"(b[1]));
}

__device__ __forceinline__ uint32_t smem_u32(const void* p) {
    return (uint32_t)__cvta_generic_to_shared(p);
}
__device__ __forceinline__ void cp_async16(uint32_t dst, const void* src) {
    asm volatile("cp.async.ca.shared.global [%0], [%1], 16;" :: "r"(dst), "l"(src));
}
#define CP_COMMIT() asm volatile("cp.async.commit_group;")
#define CP_WAIT1()  asm volatile("cp.async.wait_group 1;")

// ---------------- gather ----------------
__global__ void gather_kernel(const float* __restrict__ x,
                              const int* __restrict__ nbr,
                              float* __restrict__ inp)
{
    int idx = blockIdx.x * blockDim.x + threadIdx.x;
    if (idx >= JJ * BJ * D_IN) return;
    int j = idx / (BJ * D_IN);
    int r = idx - j * (BJ * D_IN);
    int b = r / D_IN;
    int c = r - b * D_IN;
    int t = c >> 8;
    int k = (c >> 6) & 3;
    int d = c & 63;
    int n = nbr[j * 4 + k];
    inp[idx] = x[(((size_t)b * DT_ + t) * JJ + n) * DD + d];
}

// ---------------- e1 ONLY: TF32 MMA, cp.async double-buffered ----------------
// Bit-identical operand values and mma order to R15's winning e1 chain.
// N=256 here (no N-guard needed: BN=128 divides 256). K=2304 (144 BK-tiles).
template<bool RELU>
__global__ void __launch_bounds__(256, 2) gemm_mma_e1(
    const float* __restrict__ A, const float* __restrict__ W,
    const float* __restrict__ bias, float* __restrict__ C,
    int K, int N, int a_div)
{
    constexpr int BM = 128, BN = 128, BK = 16;
    constexpr int AST = BK + 4;    // 20 floats/row
    constexpr int BST = BN + 8;    // 136 floats/row

    const int pair = blockIdx.y;
    const int n0 = blockIdx.x * BN;
    const int tid = threadIdx.x;
    const int wid = tid >> 5;
    const int lane = tid & 31;
    const int g  = lane >> 2;
    const int tg = lane & 3;
    const int wm0 = (wid & 1) * 64;
    const int wn0 = (wid >> 1) * 32;

    const float* Ap = A + (size_t)(pair / a_div) * (size_t)BM * K;
    const float* Wp = W + (size_t)pair * (size_t)K * N;
    const float* bp = bias + (size_t)pair * N;
    float* Cp = C + (size_t)pair * (size_t)BM * N;

    __shared__ float As[2][BM][AST];   // raw fp32 [m][k]
    __shared__ float Bs[2][BK][BST];   // raw fp32 [k][n]

    float acc[4][4][4];
    #pragma unroll
    for (int mi = 0; mi < 4; mi++)
        #pragma unroll
        for (int ni = 0; ni < 4; ni++)
            #pragma unroll
            for (int r = 0; r < 4; r++) acc[mi][ni][r] = 0.f;

    auto load_tiles = [&](int buf, int kk) {
        #pragma unroll
        for (int v = 0; v < 2; v++) {
            int f4i = tid * 2 + v;
            int row = f4i >> 2;
            int kc  = (f4i & 3) * 4;
            cp_async16(smem_u32(&As[buf][row][kc]), Ap + (size_t)row * K + kk + kc);
        }
        #pragma unroll
        for (int v = 0; v < 2; v++) {
            int f4i = tid * 2 + v;
            int krow = f4i >> 5;
            int nc   = (f4i & 31) * 4;
            cp_async16(smem_u32(&Bs[buf][krow][nc]),
                       Wp + (size_t)(kk + krow) * N + n0 + nc);
        }
    };

    const int nk = K / BK;
    load_tiles(0, 0);
    CP_COMMIT();

    for (int it = 0; it < nk; it++) {
        int buf = it & 1;
        if (it + 1 < nk) load_tiles(buf ^ 1, (it + 1) * BK);
        CP_COMMIT();
        CP_WAIT1();
        __syncthreads();

        #pragma unroll
        for (int ks = 0; ks < 2; ks++) {
            const int kb = ks * 8;
            uint32_t af[4][4], bf[4][2];
            #pragma unroll
            for (int mi = 0; mi < 4; mi++) {
                int mb = wm0 + mi * 16;
                af[mi][0] = __float_as_uint(tf32r(As[buf][mb + g    ][kb + tg    ]));
                af[mi][1] = __float_as_uint(tf32r(As[buf][mb + g + 8][kb + tg    ]));
                af[mi][2] = __float_as_uint(tf32r(As[buf][mb + g    ][kb + tg + 4]));
                af[mi][3] = __float_as_uint(tf32r(As[buf][mb + g + 8][kb + tg + 4]));
            }
            #pragma unroll
            for (int ni = 0; ni < 4; ni++) {
                int nb = wn0 + ni * 8;
                bf[ni][0] = __float_as_uint(tf32r(Bs[buf][kb + tg    ][nb + g]));
                bf[ni][1] = __float_as_uint(tf32r(Bs[buf][kb + tg + 4][nb + g]));
            }
            #pragma unroll
            for (int mi = 0; mi < 4; mi++)
                #pragma unroll
                for (int ni = 0; ni < 4; ni++)
                    mma_tf32(acc[mi][ni], af[mi], bf[ni]);
        }
        __syncthreads();
    }

    #pragma unroll
    for (int mi = 0; mi < 4; mi++) {
        #pragma unroll
        for (int ni = 0; ni < 4; ni++) {
            int row0 = wm0 + mi * 16 + g;
            int col0 = n0 + wn0 + ni * 8 + tg * 2;
            #pragma unroll
            for (int r = 0; r < 4; r++) {
                int row = row0 + (r >> 1) * 8;
                int col = col0 + (r & 1);
                float v = acc[mi][ni][r] + bp[col];
                if (RELU) v = fmaxf(v, 0.f);
                Cp[(size_t)row * N + col] = v;
            }
        }
    }
}

// ---------------- layers 3-7: R12-EXACT FFMA GEMM (numerics frozen; DO NOT TOUCH) ------
// Optional second problem set for fused independent GEMMs sharing A (blockIdx.y >= nb1).
template<bool RELU>
__global__ void __launch_bounds__(256, 2) gemm_bias(
    const float* __restrict__ A,
    const float* __restrict__ W,  const float* __restrict__ bias,  float* __restrict__ C,
    const float* __restrict__ W2, const float* __restrict__ bias2, float* __restrict__ C2,
    int nb1, int K, int N, int a_div)
{
    constexpr int BM = 128, BN = 128, BK = 16;
    int pr = blockIdx.y;
    const float* Wsel = W; const float* bsel = bias; float* Csel = C;
    int pair = pr;
    if (pr >= nb1) { pair = pr - nb1; Wsel = W2; bsel = bias2; Csel = C2; }

    const int n0 = blockIdx.x * BN;
    const int tid = threadIdx.x;

    const float* Ap = A + (size_t)(pair / a_div) * (size_t)BM * K;
    const float* Wp = Wsel + (size_t)pair * (size_t)K * N;
    const float* bp = bsel + (size_t)pair * N;
    float* Cp = Csel + (size_t)pair * (size_t)BM * N;

    __shared__ float As[BK][BM];
    __shared__ float Bs[BK][BN];

    const int a_row = tid >> 1;
    const int a_k   = (tid & 1) * 8;
    const int b_row = tid >> 4;
    const int b_c4  = tid & 15;

    const int rm0 = (tid >> 4) * 8;
    const int rn0 = (tid & 15) * 8;

    float acc[8][8];
    #pragma unroll
    for (int i = 0; i < 8; i++)
        #pragma unroll
        for (int j = 0; j < 8; j++) acc[i][j] = 0.f;

    for (int kk = 0; kk < K; kk += BK) {
        #pragma unroll
        for (int v = 0; v < 2; v++) {
            float4 a = *reinterpret_cast<const float4*>(
                Ap + (size_t)a_row * K + kk + a_k + v * 4);
            As[a_k + v * 4 + 0][a_row] = tf32r(a.x);
            As[a_k + v * 4 + 1][a_row] = tf32r(a.y);
            As[a_k + v * 4 + 2][a_row] = tf32r(a.z);
            As[a_k + v * 4 + 3][a_row] = tf32r(a.w);
        }
        #pragma unroll
        for (int v = 0; v < 2; v++) {
            int col = b_c4 * 4 + v * 64;
            float4 b = make_float4(0.f, 0.f, 0.f, 0.f);
            if (n0 + col < N)
                b = *reinterpret_cast<const float4*>(
                    Wp + (size_t)(kk + b_row) * N + n0 + col);
            Bs[b_row][col + 0] = tf32r(b.x);
            Bs[b_row][col + 1] = tf32r(b.y);
            Bs[b_row][col + 2] = tf32r(b.z);
            Bs[b_row][col + 3] = tf32r(b.w);
        }
        __syncthreads();

        #pragma unroll
        for (int k = 0; k < BK; k++) {
            float ra[8], rb[8];
            #pragma unroll
            for (int i = 0; i < 2; i++) {
                float4 t4 = *reinterpret_cast<const float4*>(&As[k][rm0 + i * 4]);
                ra[i*4+0] = t4.x; ra[i*4+1] = t4.y; ra[i*4+2] = t4.z; ra[i*4+3] = t4.w;
            }
            #pragma unroll
            for (int i = 0; i < 2; i++) {
                float4 t4 = *reinterpret_cast<const float4*>(&Bs[k][rn0 + i * 4]);
                rb[i*4+0] = t4.x; rb[i*4+1] = t4.y; rb[i*4+2] = t4.z; rb[i*4+3] = t4.w;
            }
            #pragma unroll
            for (int i = 0; i < 8; i++)
                #pragma unroll
                for (int j = 0; j < 8; j++)
                    acc[i][j] = fmaf(ra[i], rb[j], acc[i][j]);
        }
        __syncthreads();
    }

    #pragma unroll
    for (int j = 0; j < 8; j++) {
        int n = n0 + rn0 + j;
        if (n < N) {
            float bv = bp[n];
            #pragma unroll
            for (int i = 0; i < 8; i++) {
                float v = acc[i][j] + bv;
                if (RELU) v = fmaxf(v, 0.f);
                Cp[(size_t)(rm0 + i) * N + n] = v;
            }
        }
    }
}

// ---------------- err[p][b]: XLA:GPU row-reduction emitter order (bit-exact, DO NOT TOUCH)
__global__ void err_kernel(const float* __restrict__ xhat,
                           const float* __restrict__ x,
                           float* __restrict__ err)
{
    int w = (blockIdx.x * blockDim.x + threadIdx.x) >> 5;
    int lane = threadIdx.x & 31;
    if (w >= PAIRS * BJ) return;
    int p = w / BJ;
    int b = w - p * BJ;
    int j = p / EE;
    const float* xh = xhat + ((size_t)p * BJ + b) * D_OUT;
    const float* xb = x + (size_t)b * DT_ * JJ * DD + (size_t)j * DD;

    float acc = 0.f;
    #pragma unroll
    for (int k = 0; k < 9; k++) {
        int i0 = 2 * lane + 64 * k;
        int t0 = i0 >> 6, d0i = i0 & 63;
        int i1 = i0 + 1;
        int t1 = i1 >> 6, d1i = i1 & 63;
        float tg0 = __ldg(xb + (size_t)t0 * JJ * DD + d0i);
        float tg1 = __ldg(xb + (size_t)t1 * JJ * DD + d1i);
        float d0 = __fsub_rn(__ldg(xh + i0), tg0);
        float d1 = __fsub_rn(__ldg(xh + i1), tg1);
        acc = fmaf(d0, d0, acc);
        acc = fmaf(d1, d1, acc);
    }
    #pragma unroll
    for (int o = 16; o > 0; o >>= 1)
        acc = __fadd_rn(acc, __shfl_down_sync(0xffffffffu, acc, o));
    if (lane == 0) err[(size_t)p * BJ + b] = __fdiv_rn(acc, 576.0f);
}

// ---------------- select ----------------
#define OUT_MU   0
#define OUT_LV   360448
#define OUT_XH   720896
#define OUT_IDX  2342912
__global__ void select_kernel(const float* __restrict__ mu,
                              const float* __restrict__ lv,
                              const float* __restrict__ xhat,
                              const float* __restrict__ err,
                              float* __restrict__ out)
{
    int j = blockIdx.x;
    int b = blockIdx.y;
    int tid = threadIdx.x;  // 128

    float best = err[(size_t)(j * EE + 0) * BJ + b];
    int bi = 0;
    #pragma unroll
    for (int e = 1; e < EE; e++) {
        float v = err[(size_t)(j * EE + e) * BJ + b];
        if (v < best) { best = v; bi = e; }
    }
    int p = j * EE + bi;

    size_t base = ((size_t)b * JJ + j) * H2_;
    out[OUT_MU + base + tid] = mu[((size_t)p * BJ + b) * H2_ + tid];
    out[OUT_LV + base + tid] = lv[((size_t)p * BJ + b) * H2_ + tid];

    const float* xh = xhat + ((size_t)p * BJ + b) * D_OUT;
    for (int i = tid; i < D_OUT; i += 128) {
        int t = i >> 6, d = i & 63;
        out[OUT_XH + (((size_t)b * DT_ + t) * JJ + j) * DD + d] = xh[i];
    }
    if (tid == 0) out[OUT_IDX + (size_t)b * JJ + j] = (float)bi;
}

// ---------------- launch ----------------
extern "C" void kernel_launch(void* const* d_in, const int* in_sizes, int n_in,
                              void* d_out, int out_size)
{
    const float* x         = (const float*)d_in[0];
    const int*   neighbors = (const int*)d_in[1];
    const float* W_e1 = (const float*)d_in[2];
    const float* b_e1 = (const float*)d_in[3];
    const float* W_e2 = (const float*)d_in[4];
    const float* b_e2 = (const float*)d_in[5];
    const float* W_mu = (const float*)d_in[6];
    const float* b_mu = (const float*)d_in[7];
    const float* W_lv = (const float*)d_in[8];
    const float* b_lv = (const float*)d_in[9];
    const float* W_d1 = (const float*)d_in[10];
    const float* b_d1 = (const float*)d_in[11];
    const float* W_d2 = (const float*)d_in[12];
    const float* b_d2 = (const float*)d_in[13];
    float* out = (float*)d_out;

    float* scratch = nullptr;
    cudaGetSymbolAddress((void**)&scratch, g_scratch);
    float* errbuf = nullptr;
    cudaGetSymbolAddress((void**)&errbuf, g_err);

    float* s_inp  = scratch + OFF_INP;
    float* s_h1   = scratch + OFF_H1;
    float* s_h2   = scratch + OFF_H2;
    float* s_mu   = scratch + OFF_MU;
    float* s_lv   = scratch + OFF_LV;
    float* s_g    = scratch + OFF_G;
    float* s_xhat = scratch + OFF_XHAT;

    // 1. gather
    {
        int total = JJ * BJ * D_IN;
        gather_kernel<<<(total + 255) / 256, 256>>>(x, neighbors, s_inp);
    }
    // 2. e1: pipelined TF32 MMA (bit-identical chain to R15's winning e1)
    gemm_mma_e1<true><<<dim3(2, PAIRS), 256>>>(s_inp, W_e1, b_e1, s_h1, D_IN, H1_, EE);
    // 3. h2 = relu(h1 @ W_e2 + b_e2)    [K=256, N=128] — R12-exact FFMA
    gemm_bias<true ><<<dim3(1, PAIRS), 256>>>(s_h1, W_e2, b_e2, s_h2,
                                              nullptr, nullptr, nullptr,
                                              PAIRS, H1_, H2_, 1);
    // 4+5. mu & lv fused (scheduling only; per-output numerics identical to R12)
    gemm_bias<false><<<dim3(1, 2 * PAIRS), 256>>>(s_h2, W_mu, b_mu, s_mu,
                                                  W_lv, b_lv, s_lv,
                                                  PAIRS, H2_, H2_, 1);
    // 6. g = relu(mu @ W_d1 + b_d1)     [K=128, N=256]
    gemm_bias<true ><<<dim3(2, PAIRS), 256>>>(s_mu, W_d1, b_d1, s_g,
                                              nullptr, nullptr, nullptr,
                                              PAIRS, H2_, H1_, 1);
    // 7. xhat = g @ W_d2 + b_d2         [K=256, N=576]
    gemm_bias<false><<<dim3(5, PAIRS), 256>>>(s_g, W_d2, b_d2, s_xhat,
                                              nullptr, nullptr, nullptr,
                                              PAIRS, H1_, D_OUT, 1);
    // 8. err: XLA:GPU vec2 warp row-reduce
    {
        int warps = PAIRS * BJ;
        err_kernel<<<(warps * 32 + 255) / 256, 256>>>(s_xhat, x, errbuf);
    }
    // 9. argmin + gather outputs
    select_kernel<<<dim3(JJ, BJ), 128>>>(s_mu, s_lv, s_xhat, errbuf, out);
}